// round 16
// baseline (speedup 1.0000x reference)
#include <cuda_runtime.h>
#include <cuda_bf16.h>
#include <cstdint>
#include <cstddef>

namespace {
constexpr int kB    = 128;
constexpr int kT    = 65536;
constexpr int kE    = 512;
constexpr int kSmax = 512;

constexpr int BM = 64;
constexpr int BN = 128;
constexpr int KC = 32;

constexpr int NTHREADS = 128;   // 4 warps: 2(m) x 2(n), warp tile 32x64

constexpr int LDSF = 36;

constexpr int OFF_A = 0;                         // 64 x 36
constexpr int OFF_B = BM * LDSF;                 // 2304
constexpr int BUF_FLOATS = OFF_B + BN * LDSF;    // 6912
constexpr int SMEM_FLOATS = 2 * BUF_FLOATS;      // 13824
constexpr int SMEM_BYTES  = SMEM_FLOATS * 4;     // 55296

constexpr int NPROD  = kB * 4;                   // 512 producer blocks
constexpr int NGEMM  = (kE / BN) * (kSmax / BM) * kB;  // 4096
constexpr int NCONS  = (kE / BN) * (kSmax / BM);       // 32 consumers/sample
}

__device__ int g_nvalid[kB];
__device__ int g_cnt[kB];
__device__ int g_done[kB];
__device__ int g_ready[kB];

// ---------------------------------------------------------------------------
__device__ __forceinline__ uint32_t smem_u32(const void* p) {
    uint32_t a;
    asm("{ .reg .u64 t; cvta.to.shared.u64 t, %1; cvt.u32.u64 %0, t; }" : "=r"(a) : "l"(p));
    return a;
}

__device__ __forceinline__ void ldsm_x4(uint32_t& r0, uint32_t& r1, uint32_t& r2,
                                        uint32_t& r3, uint32_t addr) {
    asm volatile("ldmatrix.sync.aligned.m8n8.x4.shared.b16 {%0,%1,%2,%3}, [%4];"
                 : "=r"(r0), "=r"(r1), "=r"(r2), "=r"(r3) : "r"(addr));
}

__device__ __forceinline__ void mma_tf32(float* c, const uint32_t* a, const uint32_t* b) {
    asm volatile(
        "mma.sync.aligned.m16n8k8.row.col.f32.tf32.tf32.f32 "
        "{%0,%1,%2,%3}, {%4,%5,%6,%7}, {%8,%9}, {%0,%1,%2,%3};"
        : "+f"(c[0]), "+f"(c[1]), "+f"(c[2]), "+f"(c[3])
        : "r"(a[0]), "r"(a[1]), "r"(a[2]), "r"(a[3]), "r"(b[0]), "r"(b[1]));
}

__device__ __forceinline__ void cp_async16(uint32_t dst, const void* src) {
    asm volatile("cp.async.cg.shared.global [%0], [%1], 16;" :: "r"(dst), "l"(src));
}
__device__ __forceinline__ void cp_commit() {
    asm volatile("cp.async.commit_group;" ::: "memory");
}
template <int N>
__device__ __forceinline__ void cp_wait() {
    asm volatile("cp.async.wait_group %0;" :: "n"(N) : "memory");
}

// ---------------------------------------------------------------------------
// Fused kernel. Blocks [0, NPROD): mask popcount producers (dispatched first).
// Blocks [NPROD, NPROD+NGEMM): GEMM consumers, spin on g_ready[b].
// ---------------------------------------------------------------------------
__global__ __launch_bounds__(NTHREADS, 4) void fused_kernel(
    const float* __restrict__ signal,
    const int*   __restrict__ mask,
    const int*   __restrict__ branch_idx,
    const float* __restrict__ W0, const float* __restrict__ b0,
    const float* __restrict__ W1, const float* __restrict__ b1,
    const float* __restrict__ W2, const float* __restrict__ b2,
    float* __restrict__ out,
    int write_mask)
{
    extern __shared__ float smemf[];
    const int bid = blockIdx.x;
    const int tid = threadIdx.x;

    // ======================= producer blocks =======================
    if (bid < NPROD) {
        const int b = bid >> 2;
        const int q = bid & 3;

        // quarter q of sample b: 4096 uint4; 128 threads x 32 loads (2 x MLP16)
        const uint4* p = reinterpret_cast<const uint4*>(mask + (size_t)b * kT) + q * 4096;
        int sum = 0;
#pragma unroll
        for (int h = 0; h < 2; h++) {
            uint4 v[16];
#pragma unroll
            for (int j = 0; j < 16; j++) v[j] = p[tid + (h * 16 + j) * 128];
#pragma unroll
            for (int j = 0; j < 16; j++)
                sum += (int)((v[j].x & 1u) + (v[j].y & 1u) + (v[j].z & 1u) + (v[j].w & 1u));
        }
#pragma unroll
        for (int o = 16; o > 0; o >>= 1) sum += __shfl_down_sync(0xffffffffu, sum, o);

        __shared__ int warp_sums[4];
        __shared__ int is_last;
        if ((tid & 31) == 0) warp_sums[tid >> 5] = sum;
        __syncthreads();
        if (tid == 0) {
            int tot = warp_sums[0] + warp_sums[1] + warp_sums[2] + warp_sums[3];
            atomicAdd(&g_cnt[b], tot);
            __threadfence();
            int old = atomicAdd(&g_done[b], 1);
            is_last = (old == 3);
        }
        __syncthreads();
        if (!is_last) return;

        __shared__ int nv_sh;
        if (tid == 0) {
            __threadfence();
            int tot = atomicAdd(&g_cnt[b], 0);
            int bi = branch_idx[b];
            int w  = 128 << bi;
            int Sb = kT / w;
            int nv = tot / w;
            if (nv > Sb) nv = Sb;
            g_nvalid[b] = nv;
            nv_sh = nv;
            g_cnt[b]  = 0;
            g_done[b] = 0;
            __threadfence();
            atomicExch(&g_ready[b], NCONS);   // release: consumers may proceed
        }
        __syncthreads();

        if (write_mask) {
            int nv = nv_sh;
            float* mout = out + (size_t)kB * kSmax * kE + (size_t)b * kSmax;
            for (int s = tid; s < kSmax; s += NTHREADS) mout[s] = (s < nv) ? 1.0f : 0.0f;
        }
        return;
    }

    // ======================= GEMM blocks =======================
    const int lin = bid - NPROD;
    const int b   = lin >> 5;             // sample
    const int m0  = ((lin >> 2) & 7) * BM;
    const int n0  = (lin & 3) * BN;

    // acquire n_valid (producer blocks are ahead in dispatch order)
    __shared__ int nv_sh;
    if (tid == 0) {
        volatile int* rp = &g_ready[b];
        while (*rp == 0) { __nanosleep(128); }
        nv_sh = *reinterpret_cast<volatile int*>(&g_nvalid[b]);
        atomicSub(&g_ready[b], 1);        // consume (resets to 0 for next replay)
    }
    __syncthreads();
    const int nv = nv_sh;

    float* outb = out + (size_t)b * kSmax * kE;

    if (m0 >= nv) {
        float4 z = make_float4(0.f, 0.f, 0.f, 0.f);
#pragma unroll
        for (int i = 0; i < 16; i++) {
            int u   = tid + i * NTHREADS;
            int row = u >> 5;
            int c4  = (u & 31) << 2;
            *reinterpret_cast<float4*>(outb + (size_t)(m0 + row) * kE + n0 + c4) = z;
        }
        return;
    }

    const int bi   = branch_idx[b];
    const int logw = 7 + bi;
    const int nchunks = (1 << logw) / KC;
    const float* Wp = (bi == 0) ? W0 : (bi == 1) ? W1 : W2;
    const float* bp = (bi == 0) ? b0 : (bi == 1) ? b1 : b2;
    const float* Asrc = signal + (size_t)b * kT + ((size_t)m0 << logw);
    const float* Bsrc = Wp + ((size_t)n0 << logw);

    const uint32_t sbase = smem_u32(smemf);
    const int lane   = tid & 31;
    const int warp   = tid >> 5;
    const int warp_m = warp & 1;
    const int warp_n = warp >> 1;
    const int g      = lane >> 2;
    const int tg     = lane & 3;

    const int grp = lane >> 3;
    const int r8  = lane & 7;
    const uint32_t aRowBase = warp_m * 32 + (grp & 1) * 8 + r8;
    const uint32_t aColOff  = (grp >> 1) * 4;
    const uint32_t aAddr0 = sbase + (OFF_A + aRowBase * LDSF + aColOff) * 4;
    const uint32_t bRowBase = warp_n * 64 + (grp >> 1) * 8 + r8;
    const uint32_t bColOff  = (grp & 1) * 4;
    const uint32_t bAddr0 = sbase + (OFF_B + bRowBase * LDSF + bColOff) * 4;

    float acc[2][8][4];
#pragma unroll
    for (int mi = 0; mi < 2; mi++)
#pragma unroll
        for (int nj = 0; nj < 8; nj++)
#pragma unroll
            for (int q = 0; q < 4; q++) acc[mi][nj][q] = 0.f;

    const int lrow = tid >> 3;
    const int lc4  = (tid & 7) << 2;

    {
        uint32_t dA = sbase + (OFF_A + lrow * LDSF + lc4) * 4;
        uint32_t dB = sbase + (OFF_B + lrow * LDSF + lc4) * 4;
#pragma unroll
        for (int i = 0; i < 4; i++) {
            int row = lrow + i * 16;
            cp_async16(dA + i * 16 * LDSF * 4, Asrc + ((size_t)row << logw) + lc4);
        }
#pragma unroll
        for (int i = 0; i < 8; i++) {
            int row = lrow + i * 16;
            cp_async16(dB + i * 16 * LDSF * 4, Bsrc + ((size_t)row << logw) + lc4);
        }
        cp_commit();
    }

    for (int c = 0; c < nchunks; c++) {
        const uint32_t cbufB = (c & 1) * BUF_FLOATS * 4;
        const bool more = (c + 1 < nchunks);

        if (more) {
            const int kk = (c + 1) * KC;
            const uint32_t nb = ((c + 1) & 1) * BUF_FLOATS * 4;
            uint32_t dA = sbase + nb + (OFF_A + lrow * LDSF + lc4) * 4;
            uint32_t dB = sbase + nb + (OFF_B + lrow * LDSF + lc4) * 4;
#pragma unroll
            for (int i = 0; i < 4; i++) {
                int row = lrow + i * 16;
                cp_async16(dA + i * 16 * LDSF * 4, Asrc + ((size_t)row << logw) + kk + lc4);
            }
#pragma unroll
            for (int i = 0; i < 8; i++) {
                int row = lrow + i * 16;
                cp_async16(dB + i * 16 * LDSF * 4, Bsrc + ((size_t)row << logw) + kk + lc4);
            }
            cp_commit();
            cp_wait<1>();
        } else {
            cp_wait<0>();
        }
        __syncthreads();

#pragma unroll
        for (int s = 0; s < 4; s++) {
            const uint32_t ks = cbufB + s * 32;
            uint32_t af[2][4], bf[8][2];
#pragma unroll
            for (int mi = 0; mi < 2; mi++) {
                ldsm_x4(af[mi][0], af[mi][1], af[mi][2], af[mi][3],
                        aAddr0 + ks + mi * (16 * LDSF * 4));
            }
#pragma unroll
            for (int q = 0; q < 4; q++) {
                uint32_t r0, r1, r2, r3;
                ldsm_x4(r0, r1, r2, r3, bAddr0 + ks + q * (16 * LDSF * 4));
                bf[2 * q][0]     = r0;
                bf[2 * q][1]     = r1;
                bf[2 * q + 1][0] = r2;
                bf[2 * q + 1][1] = r3;
            }
#pragma unroll
            for (int mi = 0; mi < 2; mi++)
#pragma unroll
                for (int nj = 0; nj < 8; nj++)
                    mma_tf32(acc[mi][nj], af[mi], bf[nj]);
        }
        __syncthreads();
    }

    const int col0 = tg * 2;
    const int rbase = m0 + warp_m * 32 + g;
    const int ncol  = n0 + warp_n * 64;
#pragma unroll
    for (int mi = 0; mi < 2; mi++) {
        int r0 = rbase + mi * 16;
        int r1 = r0 + 8;
        bool v0 = r0 < nv, v1 = r1 < nv;
        float* o0p = outb + (size_t)r0 * kE + ncol + col0;
        float* o1p = outb + (size_t)r1 * kE + ncol + col0;
#pragma unroll
        for (int nj = 0; nj < 8; nj++) {
            float2 bias = *reinterpret_cast<const float2*>(bp + ncol + nj * 8 + col0);
            float2 o0 = v0 ? make_float2(acc[mi][nj][0] + bias.x, acc[mi][nj][1] + bias.y)
                           : make_float2(0.f, 0.f);
            float2 o1 = v1 ? make_float2(acc[mi][nj][2] + bias.x, acc[mi][nj][3] + bias.y)
                           : make_float2(0.f, 0.f);
            *reinterpret_cast<float2*>(o0p + nj * 8) = o0;
            *reinterpret_cast<float2*>(o1p + nj * 8) = o1;
        }
    }
}

// ---------------------------------------------------------------------------
extern "C" void kernel_launch(void* const* d_in, const int* in_sizes, int n_in,
                              void* d_out, int out_size)
{
    const float* signal = (const float*)d_in[0];
    const int*   mask   = (const int*)d_in[1];
    const int*   bidx   = (const int*)d_in[2];
    const float* W0 = (const float*)d_in[3];
    const float* b0 = (const float*)d_in[4];
    const float* W1 = (const float*)d_in[5];
    const float* b1 = (const float*)d_in[6];
    const float* W2 = (const float*)d_in[7];
    const float* b2 = (const float*)d_in[8];
    float* out = (float*)d_out;

    int write_mask = (out_size > kB * kSmax * kE) ? 1 : 0;

    static bool attr_set = false;
    if (!attr_set) {
        cudaFuncSetAttribute(fused_kernel,
                             cudaFuncAttributeMaxDynamicSharedMemorySize, SMEM_BYTES);
        attr_set = true;
    }
    fused_kernel<<<NPROD + NGEMM, NTHREADS, SMEM_BYTES>>>(
        signal, mask, bidx, W0, b0, W1, b1, W2, b2, out, write_mask);
}